// round 15
// baseline (speedup 1.0000x reference)
#include <cuda_runtime.h>
#include <math.h>

// ---------------------------------------------------------------------------
// VQ-VAE 3D forward:
//   x[4,1,128^3] -> conv(1->16,k4,s2,p1)+relu -> conv(16->32)+relu
//                -> conv(32->64) = z_e[4,64,16^3]
//   VQ: argmin_k |z - e_k|^2 over 512 codes (dim 64) -> quantized
//   convT(64->32)+relu -> convT(32->16)+relu -> convT(16->1)+sigmoid = x_hat
// Outputs concatenated: x_hat (8388608) | quantized (1048576) | z_e (1048576)
// ---------------------------------------------------------------------------

// scratch (allocation-free: __device__ globals)
__device__ float g_h1[4 * 16 * 64 * 64 * 64];   // 67 MB
__device__ float g_h2[4 * 32 * 32 * 32 * 32];   // 16.8 MB
__device__ float g_d1[4 * 32 * 32 * 32 * 32];   // 16.8 MB
__device__ float g_d2[4 * 16 * 64 * 64 * 64];   // 67 MB
__device__ float g_cbn[512];

// ---------------------------------------------------------------------------
// conv1: Cin=1, Cout=16, 128^3 -> 64^3, stride2 pad1 k4, relu
// block = 64 threads (ow), each thread computes all 16 Cout.
// ---------------------------------------------------------------------------
__global__ void conv1_k(const float* __restrict__ x, const float* __restrict__ w,
                        const float* __restrict__ b, float* __restrict__ y)
{
    __shared__ float wsm[16 * 64];
    __shared__ float patch[16 * 130];   // [kd*4+kh][j], j = iw+1

    const int od = blockIdx.x, oh = blockIdx.y, n = blockIdx.z;
    const int t = threadIdx.x;          // 0..63

    for (int i = t; i < 16 * 64; i += 64) wsm[i] = w[i];

    for (int i = t; i < 16 * 130; i += 64) {
        int r = i / 130, j = i - r * 130;
        int kd = r >> 2, kh = r & 3;
        int id = od * 2 - 1 + kd;
        int ih = oh * 2 - 1 + kh;
        int iw = j - 1;
        float v = 0.f;
        if ((unsigned)id < 128u && (unsigned)ih < 128u && (unsigned)iw < 128u)
            v = x[(size_t)n * 2097152 + (size_t)id * 16384 + ih * 128 + iw];
        patch[i] = v;
    }
    __syncthreads();

    float acc[16];
#pragma unroll
    for (int c = 0; c < 16; c++) acc[c] = b[c];

    const int ow = t;
#pragma unroll
    for (int kd = 0; kd < 4; kd++)
#pragma unroll
    for (int kh = 0; kh < 4; kh++)
#pragma unroll
    for (int kw = 0; kw < 4; kw++) {
        float p = patch[(kd * 4 + kh) * 130 + ow * 2 + kw];
        int wi = (kd * 4 + kh) * 4 + kw;
#pragma unroll
        for (int c = 0; c < 16; c++)
            acc[c] = fmaf(p, wsm[c * 64 + wi], acc[c]);
    }

    size_t sp = (size_t)od * 4096 + oh * 64 + ow;
#pragma unroll
    for (int c = 0; c < 16; c++)
        y[((size_t)n * 16 + c) * 262144 + sp] = fmaxf(acc[c], 0.f);
}

// ---------------------------------------------------------------------------
// generic strided conv (k4,s2,p1): block fixed (od,oh,n), threads = OUTS x (COUT/8),
// each thread computes 8 Cout at one voxel. Per-ci weight slice + input patch in SMEM.
// ---------------------------------------------------------------------------
template <int CIN, int COUT, int INS, int OUTS, bool RELU>
__global__ void conv_k(const float* __restrict__ x, const float* __restrict__ w,
                       const float* __restrict__ b, float* __restrict__ y)
{
    constexpr int CG = COUT / 8;
    constexpr int NT = OUTS * CG;
    constexpr int PW = OUTS * 2 + 2;
    static_assert(NT == 128, "block must be 128 threads");

    __shared__ float wsm[COUT * 64];
    __shared__ float patch[16 * PW];

    const int od = blockIdx.x, oh = blockIdx.y, n = blockIdx.z;
    const int t = threadIdx.x;
    const int ow = t & (OUTS - 1);
    const int cg = t / OUTS;
    const int co0 = cg * 8;

    float acc[8];
#pragma unroll
    for (int i = 0; i < 8; i++) acc[i] = b[co0 + i];

    for (int ci = 0; ci < CIN; ci++) {
        __syncthreads();
        for (int i = t; i < COUT * 64; i += NT) {
            int co = i >> 6, tap = i & 63;
            wsm[i] = w[((size_t)co * CIN + ci) * 64 + tap];
        }
        for (int i = t; i < 16 * PW; i += NT) {
            int r = i / PW, j = i - r * PW;
            int kd = r >> 2, kh = r & 3;
            int id = od * 2 - 1 + kd;
            int ih = oh * 2 - 1 + kh;
            int iw = j - 1;
            float v = 0.f;
            if ((unsigned)id < (unsigned)INS && (unsigned)ih < (unsigned)INS &&
                (unsigned)iw < (unsigned)INS)
                v = x[((size_t)(n * CIN + ci) * INS + id) * (INS * INS) + ih * INS + iw];
            patch[i] = v;
        }
        __syncthreads();

#pragma unroll
        for (int kd = 0; kd < 4; kd++)
#pragma unroll
        for (int kh = 0; kh < 4; kh++)
#pragma unroll
        for (int kw = 0; kw < 4; kw++) {
            float p = patch[(kd * 4 + kh) * PW + ow * 2 + kw];
            int wi = (kd * 4 + kh) * 4 + kw;
#pragma unroll
            for (int i = 0; i < 8; i++)
                acc[i] = fmaf(p, wsm[(co0 + i) * 64 + wi], acc[i]);
        }
    }

    size_t sp = (size_t)od * (OUTS * OUTS) + oh * OUTS + ow;
#pragma unroll
    for (int i = 0; i < 8; i++) {
        float v = acc[i];
        if (RELU) v = fmaxf(v, 0.f);
        y[((size_t)n * COUT + co0 + i) * ((size_t)OUTS * OUTS * OUTS) + sp] = v;
    }
}

// ---------------------------------------------------------------------------
// VQ: codebook norms, then per-position argmin + gather.
// ---------------------------------------------------------------------------
__global__ void vqnorm_k(const float* __restrict__ cb)
{
    int k = threadIdx.x;   // 512 threads
    if (k < 512) {
        float s = 0.f;
#pragma unroll
        for (int c = 0; c < 64; c++) {
            float v = cb[k * 64 + c];
            s = fmaf(v, v, s);
        }
        g_cbn[k] = s;
    }
}

__global__ void vq_k(const float* __restrict__ cb, const float* __restrict__ ze,
                     float* __restrict__ q)
{
    __shared__ float cbs[128 * 64];   // 32 KB codebook tile
    __shared__ float cbn_s[512];

    const int n = blockIdx.y;
    const int p = blockIdx.x * 128 + threadIdx.x;   // 0..4095

    float z[64];
    const float* zb = ze + (size_t)n * 64 * 4096 + p;
#pragma unroll
    for (int c = 0; c < 64; c++) z[c] = zb[(size_t)c * 4096];

    for (int i = threadIdx.x; i < 512; i += 128) cbn_s[i] = g_cbn[i];

    float best = INFINITY;
    int bk = 0;
    for (int kt = 0; kt < 4; kt++) {
        __syncthreads();
        for (int i = threadIdx.x; i < 128 * 64; i += 128)
            cbs[i] = cb[kt * 128 * 64 + i];
        __syncthreads();
        for (int kk = 0; kk < 128; kk++) {
            float dot = 0.f;
#pragma unroll
            for (int c = 0; c < 64; c++)
                dot = fmaf(z[c], cbs[kk * 64 + c], dot);
            float s = cbn_s[kt * 128 + kk] - 2.f * dot;
            if (s < best) { best = s; bk = kt * 128 + kk; }   // first-min tie-break
        }
    }

    float* qb = q + (size_t)n * 64 * 4096 + p;
    const float* crow = cb + (size_t)bk * 64;
#pragma unroll
    for (int c = 0; c < 64; c++) qb[(size_t)c * 4096] = crow[c];
}

// ---------------------------------------------------------------------------
// generic transposed conv (k4,s2,p1): y[o] += x[(o+1-k)/2] * w[ci][co][k] for
// k parity-matched to (o+1). Per block (od,oh,n fixed) only kd,kh parities pd,ph
// occur; kw needs both parities (varies per thread). COT outputs per thread.
// ACT: 0=none, 1=relu, 2=sigmoid
// ---------------------------------------------------------------------------
template <int CIN, int COUT, int INS, int OUTS, int COT, int ACT>
__global__ void convt_k(const float* __restrict__ x, const float* __restrict__ w,
                        const float* __restrict__ bias, float* __restrict__ y)
{
    constexpr int CG = COUT / COT;
    constexpr int NT = OUTS * CG;
    constexpr int PJ = OUTS / 2 + 2;
    constexpr int CC = 8;   // ci chunk
    static_assert(NT == 128, "block must be 128 threads");
    static_assert(CIN % CC == 0, "CIN divisible by chunk");

    __shared__ float wsm[CC * COUT * 16];   // [cc][co][kdn][khn][kw]
    __shared__ float patch[CC * 4 * PJ];    // [cc][di][hi][j]

    const int od = blockIdx.x, oh = blockIdx.y, n = blockIdx.z;
    const int t = threadIdx.x;
    const int ow = t & (OUTS - 1);
    const int cg = t / OUTS;
    const int co0 = cg * COT;

    const int pd = (od + 1) & 1, ph = (oh + 1) & 1;
    const int bd = (od + 1) >> 1, bh = (oh + 1) >> 1;
    const int pw = (ow + 1) & 1, bw = (ow + 1) >> 1;

    float acc[COT];
#pragma unroll
    for (int i = 0; i < COT; i++) acc[i] = bias[co0 + i];

    for (int ch = 0; ch < CIN / CC; ch++) {
        const int ci0 = ch * CC;
        __syncthreads();
        for (int idx = t; idx < CC * COUT * 16; idx += NT) {
            int cc = idx / (COUT * 16);
            int r = idx - cc * (COUT * 16);
            int co = r >> 4;
            int r2 = r & 15;
            int kdn = r2 >> 3, khn = (r2 >> 2) & 1, kw = r2 & 3;
            wsm[idx] = w[((((size_t)(ci0 + cc) * COUT + co) * 4 + (pd + 2 * kdn)) * 4 +
                          (ph + 2 * khn)) * 4 + kw];
        }
        for (int idx = t; idx < CC * 4 * PJ; idx += NT) {
            int cc = idx / (4 * PJ);
            int r = idx - cc * (4 * PJ);
            int di = r / (2 * PJ);
            int r2 = r - di * (2 * PJ);
            int hi = r2 / PJ;
            int j = r2 - hi * PJ;
            int id = bd - di, ih = bh - hi, iw = j - 1;
            float v = 0.f;
            if ((unsigned)id < (unsigned)INS && (unsigned)ih < (unsigned)INS &&
                (unsigned)iw < (unsigned)INS)
                v = x[((size_t)(n * CIN + ci0 + cc) * INS + id) * (INS * INS) + ih * INS + iw];
            patch[idx] = v;
        }
        __syncthreads();

#pragma unroll
        for (int cc = 0; cc < CC; cc++) {
#pragma unroll
            for (int kdn = 0; kdn < 2; kdn++)
#pragma unroll
            for (int khn = 0; khn < 2; khn++)
#pragma unroll
            for (int kwn = 0; kwn < 2; kwn++) {
                float p = patch[((cc * 2 + kdn) * 2 + khn) * PJ + (bw - kwn + 1)];
                int kw = pw + 2 * kwn;
#pragma unroll
                for (int i = 0; i < COT; i++)
                    acc[i] = fmaf(
                        p, wsm[(((cc * COUT + co0 + i) * 2 + kdn) * 2 + khn) * 4 + kw],
                        acc[i]);
            }
        }
    }

    size_t sp = (size_t)od * (OUTS * OUTS) + oh * OUTS + ow;
#pragma unroll
    for (int i = 0; i < COT; i++) {
        float v = acc[i];
        if (ACT == 1) v = fmaxf(v, 0.f);
        if (ACT == 2) v = 1.f / (1.f + expf(-v));
        y[((size_t)n * COUT + co0 + i) * ((size_t)OUTS * OUTS * OUTS) + sp] = v;
    }
}

// ---------------------------------------------------------------------------
extern "C" void kernel_launch(void* const* d_in, const int* in_sizes, int n_in,
                              void* d_out, int out_size)
{
    (void)in_sizes; (void)n_in; (void)out_size;

    const float* x   = (const float*)d_in[0];
    const float* w1  = (const float*)d_in[1];
    const float* b1  = (const float*)d_in[2];
    const float* w2  = (const float*)d_in[3];
    const float* b2  = (const float*)d_in[4];
    const float* w3  = (const float*)d_in[5];
    const float* b3  = (const float*)d_in[6];
    const float* cb  = (const float*)d_in[7];
    const float* dw1 = (const float*)d_in[8];
    const float* db1 = (const float*)d_in[9];
    const float* dw2 = (const float*)d_in[10];
    const float* db2 = (const float*)d_in[11];
    const float* dw3 = (const float*)d_in[12];
    const float* db3 = (const float*)d_in[13];

    float* out = (float*)d_out;
    float* x_hat = out;                 // 4*1*128^3   = 8388608
    float* q     = out + 8388608;       // 4*64*16^3   = 1048576
    float* ze    = out + 9437184;       // 4*64*16^3   = 1048576

    float *h1, *h2, *dd1, *dd2;
    cudaGetSymbolAddress((void**)&h1,  g_h1);
    cudaGetSymbolAddress((void**)&h2,  g_h2);
    cudaGetSymbolAddress((void**)&dd1, g_d1);
    cudaGetSymbolAddress((void**)&dd2, g_d2);

    // encoder
    conv1_k<<<dim3(64, 64, 4), 64>>>(x, w1, b1, h1);
    conv_k<16, 32, 64, 32, true ><<<dim3(32, 32, 4), 128>>>(h1, w2, b2, h2);
    conv_k<32, 64, 32, 16, false><<<dim3(16, 16, 4), 128>>>(h2, w3, b3, ze);

    // vector quantization
    vqnorm_k<<<1, 512>>>(cb);
    vq_k<<<dim3(32, 4), 128>>>(cb, ze, q);

    // decoder
    convt_k<64, 32, 16,  32, 8, 1><<<dim3(32, 32, 4),   128>>>(q,   dw1, db1, dd1);
    convt_k<32, 16, 32,  64, 8, 1><<<dim3(64, 64, 4),   128>>>(dd1, dw2, db2, dd2);
    convt_k<16,  1, 64, 128, 1, 2><<<dim3(128, 128, 4), 128>>>(dd2, dw3, db3, x_hat);
}

// round 16
// speedup vs baseline: 1.5857x; 1.5857x over previous
#include <cuda_runtime.h>
#include <math.h>

// ---------------------------------------------------------------------------
// VQ-VAE 3D forward, round 15: voxel-register-tiled (4 voxels x 8 Cout per
// thread) so weight LDS is amortized 4x -> FMA-pipe bound instead of LDS bound.
// ---------------------------------------------------------------------------

// scratch (allocation-free: __device__ globals)
__device__ float g_h1[4 * 16 * 64 * 64 * 64];   // 67 MB
__device__ float g_h2[4 * 32 * 32 * 32 * 32];   // 16.8 MB
__device__ float g_d1[4 * 32 * 32 * 32 * 32];   // 16.8 MB
__device__ float g_d2[4 * 16 * 64 * 64 * 64];   // 67 MB
__device__ float g_wT[328704];                  // transposed weights

// g_wT layout offsets (floats):
//   w1T  @ 0       size 1024    [ci=1 ][64][co=16]
//   w2T  @ 1024    size 32768   [ci=16][64][co=32]
//   w3T  @ 33792   size 131072  [ci=32][64][co=64]
//   dw1T @ 164864  size 131072  [ci=64][64][co=32]
//   dw2T @ 295936  size 32768   [ci=32][64][co=16]

// ---------------------------------------------------------------------------
// weight transposes: conv (OIDHW: w[co][ci][tap]) and convT (w[ci][co][tap])
// both -> wT[ci][tap][co]
// ---------------------------------------------------------------------------
__global__ void transp_oihw(const float* __restrict__ w, float* __restrict__ o,
                            int CIN, int COUT)
{
    int idx = blockIdx.x * 256 + threadIdx.x;
    if (idx >= CIN * COUT * 64) return;
    int co = idx / (CIN * 64);
    int r  = idx - co * CIN * 64;
    int ci = r >> 6, tap = r & 63;
    o[(ci * 64 + tap) * COUT + co] = w[idx];
}

__global__ void transp_iohw(const float* __restrict__ w, float* __restrict__ o,
                            int CIN, int COUT)
{
    int idx = blockIdx.x * 256 + threadIdx.x;
    if (idx >= CIN * COUT * 64) return;
    int ci = idx / (COUT * 64);
    int r  = idx - ci * COUT * 64;
    int co = r >> 6, tap = r & 63;
    o[(ci * 64 + tap) * COUT + co] = w[idx];
}

// ---------------------------------------------------------------------------
// strided conv k4 s2 p1. Thread computes VT=OUTS/Q voxels (ow = q + Q*v) for
// 8 output channels (co = cg + CG*i). Block = Q*CG*OH_T threads, warp-uniform
// ohi -> conflict-free patch broadcast; co consecutive -> conflict-free wsm.
// ---------------------------------------------------------------------------
template <int CIN, int COUT, int INS, int OUTS, int CG, int Q, int OH_T, bool RELU>
__global__ void __launch_bounds__(Q * CG * OH_T) conv_k(
    const float* __restrict__ x, const float* __restrict__ wT,
    const float* __restrict__ b, float* __restrict__ y)
{
    constexpr int NT = Q * CG * OH_T;
    constexpr int VT = OUTS / Q;
    constexpr int IH = 2 * OH_T + 2;
    constexpr int PW = 2 * OUTS + 2;

    __shared__ float wsm[64 * COUT];        // [tap][co]
    __shared__ float patch[4 * IH * PW];    // [kd][ih][iw+1]

    const int od = blockIdx.x, oh0 = blockIdx.y * OH_T, n = blockIdx.z;
    const int t = threadIdx.x;
    const int q = t % Q;
    const int cg = (t / Q) % CG;
    const int ohi = t / (Q * CG);

    float acc[VT][8];
#pragma unroll
    for (int v = 0; v < VT; v++)
#pragma unroll
        for (int i = 0; i < 8; i++) acc[v][i] = b[cg + CG * i];

    for (int ci = 0; ci < CIN; ci++) {
        __syncthreads();
        for (int idx = t; idx < 64 * COUT; idx += NT)
            wsm[idx] = wT[ci * 64 * COUT + idx];
        const float* xs = x + (size_t)(n * CIN + ci) * INS * INS * INS;
        for (int idx = t; idx < 4 * IH * PW; idx += NT) {
            int kd = idx / (IH * PW);
            int r  = (idx / PW) % IH;
            int j  = idx % PW;
            int id = 2 * od - 1 + kd;
            int ih = 2 * oh0 - 1 + r;
            int iw = j - 1;
            float v = 0.f;
            if ((unsigned)id < (unsigned)INS && (unsigned)ih < (unsigned)INS &&
                (unsigned)iw < (unsigned)INS)
                v = xs[(id * INS + ih) * INS + iw];
            patch[idx] = v;
        }
        __syncthreads();

#pragma unroll 1
        for (int kd = 0; kd < 4; kd++) {
#pragma unroll
            for (int kh = 0; kh < 4; kh++) {
                const float* prow = patch + (kd * IH + 2 * ohi + kh) * PW;
#pragma unroll
                for (int kw = 0; kw < 4; kw++) {
                    float pv[VT];
#pragma unroll
                    for (int v = 0; v < VT; v++)
                        pv[v] = prow[2 * (q + Q * v) + kw];
                    const float* wrow = wsm + ((kd * 4 + kh) * 4 + kw) * COUT + cg;
                    float wv[8];
#pragma unroll
                    for (int i = 0; i < 8; i++) wv[i] = wrow[CG * i];
#pragma unroll
                    for (int v = 0; v < VT; v++)
#pragma unroll
                        for (int i = 0; i < 8; i++)
                            acc[v][i] = fmaf(pv[v], wv[i], acc[v][i]);
                }
            }
        }
    }

    const size_t plane = (size_t)OUTS * OUTS;
#pragma unroll
    for (int i = 0; i < 8; i++) {
        float* yr = y + ((size_t)(n * COUT + cg + CG * i) * OUTS + od) * plane
                      + (oh0 + ohi) * OUTS + q;
#pragma unroll
        for (int v = 0; v < VT; v++) {
            float val = acc[v][i];
            if (RELU) val = fmaxf(val, 0.f);
            yr[Q * v] = val;
        }
    }
}

// ---------------------------------------------------------------------------
// VQ: per-position argmin over 512 codes, float4 codebook dots, per-tile norms.
// ---------------------------------------------------------------------------
__global__ void __launch_bounds__(128) vq_k(const float* __restrict__ cb,
        const float* __restrict__ ze, float* __restrict__ qo)
{
    __shared__ __align__(16) float4 cbs[128 * 16];   // 128 codes x 64 floats
    __shared__ float cbn_s[128];

    const int n = blockIdx.y;
    const int p = blockIdx.x * 128 + threadIdx.x;
    const int t = threadIdx.x;

    float z[64];
    const float* zb = ze + (size_t)n * 64 * 4096 + p;
#pragma unroll
    for (int c = 0; c < 64; c++) z[c] = zb[(size_t)c * 4096];

    float best = INFINITY;
    int bk = 0;
    const float4* cb4 = (const float4*)cb;
    for (int kt = 0; kt < 4; kt++) {
        __syncthreads();
        for (int idx = t; idx < 2048; idx += 128) cbs[idx] = cb4[kt * 2048 + idx];
        __syncthreads();
        {
            float s = 0.f;
#pragma unroll
            for (int j = 0; j < 16; j++) {
                float4 c = cbs[t * 16 + j];
                s = fmaf(c.x, c.x, s); s = fmaf(c.y, c.y, s);
                s = fmaf(c.z, c.z, s); s = fmaf(c.w, c.w, s);
            }
            cbn_s[t] = s;
        }
        __syncthreads();
        for (int kk = 0; kk < 128; kk++) {
            float d0 = 0.f, d1 = 0.f;
#pragma unroll
            for (int j = 0; j < 16; j++) {
                float4 c = cbs[kk * 16 + j];
                d0 = fmaf(z[4 * j + 0], c.x, d0);
                d1 = fmaf(z[4 * j + 1], c.y, d1);
                d0 = fmaf(z[4 * j + 2], c.z, d0);
                d1 = fmaf(z[4 * j + 3], c.w, d1);
            }
            float s = cbn_s[kk] - 2.f * (d0 + d1);
            if (s < best) { best = s; bk = kt * 128 + kk; }   // first-min tie-break
        }
    }

    float* qb = qo + (size_t)n * 64 * 4096 + p;
    const float* crow = cb + (size_t)bk * 64;
#pragma unroll
    for (int c = 0; c < 64; c++) qb[(size_t)c * 4096] = crow[c];
}

// ---------------------------------------------------------------------------
// transposed conv k4 s2 p1: y[o] += x[bd-kn] * w[k = p + 2kn]. Thread: VT
// voxels (ow = q + Q*v, parity-uniform since Q even) x 8 Cout.
// wsm groups padded to PWS = COUT+4 so even/odd-pw lanes hit distinct banks.
// ---------------------------------------------------------------------------
template <int CIN, int COUT, int INS, int OUTS, int CG, int Q, int OH_T, int CC, int ACT>
__global__ void __launch_bounds__(Q * CG * OH_T) convt_k(
    const float* __restrict__ x, const float* __restrict__ wT,
    const float* __restrict__ bias, float* __restrict__ y)
{
    constexpr int NT = Q * CG * OH_T;
    constexpr int VT = OUTS / Q;
    constexpr int IH = OH_T / 2 + 2;
    constexpr int PJ = OUTS / 2 + 2;
    constexpr int PWS = COUT + 4;

    __shared__ float wsm[CC * 32 * PWS];     // [cc][kdn][kh][kwn][pw][PWS]
    __shared__ float patch[CC * 2 * IH * PJ];

    const int od = blockIdx.x, oh0 = blockIdx.y * OH_T, n = blockIdx.z;
    const int t = threadIdx.x;
    const int q = t % Q;
    const int cg = (t / Q) % CG;
    const int ohi = t / (Q * CG);

    const int pd = (od + 1) & 1, bd = (od + 1) >> 1;
    const int pw = (q + 1) & 1,  bw0 = (q + 1) >> 1;
    const int ph = (ohi + 1) & 1;             // oh0 even
    const int rh = ((ohi + 1) >> 1) + 1;      // local bh row

    float acc[VT][8];
#pragma unroll
    for (int v = 0; v < VT; v++)
#pragma unroll
        for (int i = 0; i < 8; i++) acc[v][i] = bias[cg + CG * i];

    for (int ch = 0; ch < CIN / CC; ch++) {
        const int ci0 = ch * CC;
        __syncthreads();
        for (int idx = t; idx < CC * 32 * COUT; idx += NT) {
            int co  = idx % COUT;
            int r   = idx / COUT;
            int pww = r & 1;
            int kwn = (r >> 1) & 1;
            int kh  = (r >> 2) & 3;
            int kdn = (r >> 4) & 1;
            int cc  = r >> 5;
            int kd = pd + 2 * kdn, kw = pww + 2 * kwn;
            wsm[r * PWS + co] =
                wT[((ci0 + cc) * 64 + kd * 16 + kh * 4 + kw) * COUT + co];
        }
        for (int idx = t; idx < CC * 2 * IH * PJ; idx += NT) {
            int j  = idx % PJ;
            int r2 = idx / PJ;
            int r  = r2 % IH;
            int di = (r2 / IH) & 1;
            int cc = r2 / (IH * 2);
            int id = bd - di;
            int ih = oh0 / 2 - 1 + r;
            int iw = j - 1;
            float v = 0.f;
            if ((unsigned)id < (unsigned)INS && (unsigned)ih < (unsigned)INS &&
                (unsigned)iw < (unsigned)INS)
                v = x[((size_t)(n * CIN + ci0 + cc) * INS + id) * (INS * INS)
                      + ih * INS + iw];
            patch[idx] = v;
        }
        __syncthreads();

#pragma unroll 1
        for (int cc = 0; cc < CC; cc++) {
#pragma unroll
            for (int kdn = 0; kdn < 2; kdn++) {
#pragma unroll
                for (int khn = 0; khn < 2; khn++) {
                    const float* prow =
                        patch + ((cc * 2 + kdn) * IH + (rh - khn)) * PJ;
                    const int kh = ph + 2 * khn;
#pragma unroll
                    for (int kwn = 0; kwn < 2; kwn++) {
                        const float* wrow = wsm +
                            ((((cc * 2 + kdn) * 4 + kh) * 2 + kwn) * 2 + pw) * PWS + cg;
                        float wv[8];
#pragma unroll
                        for (int i = 0; i < 8; i++) wv[i] = wrow[CG * i];
                        float pv[VT];
#pragma unroll
                        for (int v = 0; v < VT; v++)
                            pv[v] = prow[bw0 + (Q / 2) * v - kwn + 1];
#pragma unroll
                        for (int v = 0; v < VT; v++)
#pragma unroll
                            for (int i = 0; i < 8; i++)
                                acc[v][i] = fmaf(pv[v], wv[i], acc[v][i]);
                    }
                }
            }
        }
    }

    const size_t plane = (size_t)OUTS * OUTS;
#pragma unroll
    for (int i = 0; i < 8; i++) {
        float* yr = y + ((size_t)(n * COUT + cg + CG * i) * OUTS + od) * plane
                      + (oh0 + ohi) * OUTS + q;
#pragma unroll
        for (int v = 0; v < VT; v++) {
            float val = acc[v][i];
            if (ACT == 1) val = fmaxf(val, 0.f);
            yr[Q * v] = val;
        }
    }
}

// ---------------------------------------------------------------------------
// convT3: 16->1, 64^3 -> 128^3, sigmoid. Thread computes 8 contiguous ow
// (ow = 8q + v): patch row kept in regs (float4+float2), all 4 kw weights in
// one float4 -> LDS:FMA ~ 10:16.
// ---------------------------------------------------------------------------
__global__ void __launch_bounds__(128) convt3_k(const float* __restrict__ x,
    const float* __restrict__ w, const float* __restrict__ bias,
    float* __restrict__ y)
{
    constexpr int CC = 8;
    constexpr int IH = 6;       // OH_T = 8
    constexpr int PJP = 68;     // 66 used cols, padded to mult-of-4

    __shared__ __align__(16) float wsm[16 * 64];
    __shared__ __align__(16) float patch[CC * 2 * IH * PJP];

    const int od = blockIdx.x, oh0 = blockIdx.y * 8, n = blockIdx.z;
    const int t = threadIdx.x;
    const int q = t & 15, ohi = t >> 4;

    const int pd = (od + 1) & 1, bd = (od + 1) >> 1;
    const int ph = (ohi + 1) & 1;
    const int rh = ((ohi + 1) >> 1) + 1;

    for (int idx = t; idx < 1024; idx += 128) wsm[idx] = w[idx];

    float acc[8];
    const float b0 = bias[0];
#pragma unroll
    for (int v = 0; v < 8; v++) acc[v] = b0;

    for (int ch = 0; ch < 2; ch++) {
        __syncthreads();
        for (int idx = t; idx < CC * 2 * IH * 66; idx += 128) {
            int j  = idx % 66;
            int r2 = idx / 66;
            int r  = r2 % IH;
            int di = (r2 / IH) & 1;
            int cc = r2 / (IH * 2);
            int id = bd - di;
            int ih = oh0 / 2 - 1 + r;
            int iw = j - 1;
            float v = 0.f;
            if ((unsigned)id < 64u && (unsigned)ih < 64u && (unsigned)iw < 64u)
                v = x[((size_t)(n * 16 + ch * CC + cc) * 64 + id) * 4096
                      + ih * 64 + iw];
            patch[r2 * PJP + j] = v;
        }
        __syncthreads();

#pragma unroll 1
        for (int cc = 0; cc < CC; cc++) {
#pragma unroll
            for (int kdn = 0; kdn < 2; kdn++) {
#pragma unroll
                for (int khn = 0; khn < 2; khn++) {
                    const int kd = pd + 2 * kdn, kh = ph + 2 * khn;
                    const float4 wq =
                        *(const float4*)&wsm[(ch * CC + cc) * 64 + kd * 16 + kh * 4];
                    const float* prow =
                        patch + ((cc * 2 + kdn) * IH + (rh - khn)) * PJP + 4 * q;
                    float4 pa = *(const float4*)prow;
                    float2 pb = *(const float2*)(prow + 4);
                    float p[6] = {pa.x, pa.y, pa.z, pa.w, pb.x, pb.y};
#pragma unroll
                    for (int v = 0; v < 8; v++) {
                        const int bwp = (v + 1) >> 1;
                        const float w0 = ((v + 1) & 1) ? wq.y : wq.x;  // kw = pw
                        const float w1 = ((v + 1) & 1) ? wq.w : wq.z;  // kw = pw+2
                        acc[v] = fmaf(p[bwp + 1], w0, acc[v]);
                        acc[v] = fmaf(p[bwp],     w1, acc[v]);
                    }
                }
            }
        }
    }

#pragma unroll
    for (int v = 0; v < 8; v++) {
        float s = 1.f / (1.f + __expf(-acc[v]));
        y[((size_t)n * 128 + od) * 16384 + (oh0 + ohi) * 128 + 8 * q + v] = s;
    }
}

// ---------------------------------------------------------------------------
extern "C" void kernel_launch(void* const* d_in, const int* in_sizes, int n_in,
                              void* d_out, int out_size)
{
    (void)in_sizes; (void)n_in; (void)out_size;

    const float* x   = (const float*)d_in[0];
    const float* w1  = (const float*)d_in[1];
    const float* b1  = (const float*)d_in[2];
    const float* w2  = (const float*)d_in[3];
    const float* b2  = (const float*)d_in[4];
    const float* w3  = (const float*)d_in[5];
    const float* b3  = (const float*)d_in[6];
    const float* cb  = (const float*)d_in[7];
    const float* dw1 = (const float*)d_in[8];
    const float* db1 = (const float*)d_in[9];
    const float* dw2 = (const float*)d_in[10];
    const float* db2 = (const float*)d_in[11];
    const float* dw3 = (const float*)d_in[12];
    const float* db3 = (const float*)d_in[13];

    float* out = (float*)d_out;
    float* x_hat = out;                 // 4*1*128^3   = 8388608
    float* qq    = out + 8388608;       // 4*64*16^3   = 1048576
    float* ze    = out + 9437184;       // 4*64*16^3   = 1048576

    float *h1, *h2, *dd1, *dd2, *wT;
    cudaGetSymbolAddress((void**)&h1,  g_h1);
    cudaGetSymbolAddress((void**)&h2,  g_h2);
    cudaGetSymbolAddress((void**)&dd1, g_d1);
    cudaGetSymbolAddress((void**)&dd2, g_d2);
    cudaGetSymbolAddress((void**)&wT,  g_wT);

    float* w1T  = wT;
    float* w2T  = wT + 1024;
    float* w3T  = wT + 33792;
    float* dw1T = wT + 164864;
    float* dw2T = wT + 295936;

    // weight transposes
    transp_oihw<<<(1024   + 255) / 256, 256>>>(w1,  w1T,  1,  16);
    transp_oihw<<<(32768  + 255) / 256, 256>>>(w2,  w2T,  16, 32);
    transp_oihw<<<(131072 + 255) / 256, 256>>>(w3,  w3T,  32, 64);
    transp_iohw<<<(131072 + 255) / 256, 256>>>(dw1, dw1T, 64, 32);
    transp_iohw<<<(32768  + 255) / 256, 256>>>(dw2, dw2T, 32, 16);

    // encoder
    conv_k<1, 16, 128, 64, 2, 16, 4, true ><<<dim3(64, 16, 4), 128>>>(x,  w1T, b1, h1);
    conv_k<16, 32, 64, 32, 4, 8,  4, true ><<<dim3(32, 8, 4),  128>>>(h1, w2T, b2, h2);
    conv_k<32, 64, 32, 16, 8, 4,  2, false><<<dim3(16, 8, 4),   64>>>(h2, w3T, b3, ze);

    // vector quantization
    vq_k<<<dim3(32, 4), 128>>>(cb, ze, qq);

    // decoder
    convt_k<64, 32, 16, 32, 4, 8,  4, 4, 1><<<dim3(32, 8, 4),  128>>>(qq,  dw1T, db1, dd1);
    convt_k<32, 16, 32, 64, 2, 16, 4, 8, 1><<<dim3(64, 16, 4), 128>>>(dd1, dw2T, db2, dd2);
    convt3_k<<<dim3(128, 16, 4), 128>>>(dd2, dw3, db3, x_hat);
}